// round 12
// baseline (speedup 1.0000x reference)
#include <cuda_runtime.h>
#include <math.h>
#include <stdint.h>

// ---------------------------------------------------------------------------
// MoELayer: B=65536 tokens, D=256, E=16 experts, H=256, O=256, TOP_K=2
// out = [ y (B*O floats) | p (B*E floats) ]
// R8: all GEMM inner loops use packed fma.rn.f32x2 (FFMA2) -> 2x fp32 FMA rate
// ---------------------------------------------------------------------------

#define BATCH   65536
#define DIM     256
#define NEXP    16
#define HID     256
#define OUTD    256
#define GHID    1024   // 4*D

typedef unsigned long long u64;

// ---------------- packed f32x2 helpers (sm_103a) -----------------------------
__device__ __forceinline__ u64 bcast2(float x) {
    u64 r; asm("mov.b64 %0, {%1, %1};" : "=l"(r) : "f"(x)); return r;
}
__device__ __forceinline__ void ffma2(u64& d, u64 a, u64 b) {
    asm("fma.rn.f32x2 %0, %1, %2, %0;" : "+l"(d) : "l"(a), "l"(b));
}
__device__ __forceinline__ float2 unpack2(u64 v) {
    float2 f; asm("mov.b64 {%0, %1}, %2;" : "=f"(f.x), "=f"(f.y) : "l"(v)); return f;
}

// ---------------- scratch (device globals; no allocations allowed) ----------
__device__ float    g_Y1[(size_t)BATCH * GHID];    // 256 MB gate hidden 1
__device__ float    g_Y2[(size_t)BATCH * DIM];     //  64 MB gate hidden 2
__device__ float    g_w[BATCH * 2];                // renormalized top-2 weights
__device__ int      g_eidx[BATCH * 2];             // top-2 expert ids
__device__ int      g_counts[NEXP];
__device__ int      g_offsets[NEXP + 1];
__device__ int      g_cursor[NEXP];
__device__ unsigned g_list[BATCH * 2];             // entry = token*2 + slot
__device__ float    g_yslots[(size_t)BATCH * 2 * OUTD];  // 128 MB per-slot out

// ---------------------------------------------------------------------------
__global__ void k_zero() {
    int i = threadIdx.x;
    if (i < NEXP) g_counts[i] = 0;
}

// ---------------------------------------------------------------------------
// Generic fp32 GEMM via FFMA2: C = relu(A[M,K] @ B[K,N] + bias[N])
// tile 128x256, BK=16, 512 threads, 8x8 per thread (accs packed 8x4 f32x2).
// ---------------------------------------------------------------------------
__global__ __launch_bounds__(512, 1)
void k_gemm_bias_relu(const float* __restrict__ A, const float* __restrict__ B,
                      const float* __restrict__ bv, float* __restrict__ C,
                      int M, int N, int K)
{
    __shared__ float As[16 * 128];
    __shared__ float Bs[16 * 256];

    const int tid = threadIdx.x;
    const int tx = tid & 31;        // n-group (0..31) -> 8 cols each
    const int ty = tid >> 5;        // m-group (0..15) -> 8 rows each
    const int m0 = blockIdx.y * 128;
    const int n0 = blockIdx.x * 256;

    const int a_r = tid >> 2;              // 0..127
    const int a_c = (tid & 3) << 2;        // 0,4,8,12
    const int b_r = tid >> 6;              // 0..7
    const int b_c = (tid & 63) << 2;       // 0..252

    const float* Arow = A + (size_t)(m0 + a_r) * K + a_c;
    const float* Bp   = B + (size_t)b_r * N + n0 + b_c;

    u64 acc[8][4];
#pragma unroll
    for (int i = 0; i < 8; i++)
#pragma unroll
        for (int j = 0; j < 4; j++) acc[i][j] = 0ull;

    for (int k0 = 0; k0 < K; k0 += 16) {
        float4 av = *(const float4*)(Arow + k0);
        As[(a_c + 0) * 128 + a_r] = av.x;
        As[(a_c + 1) * 128 + a_r] = av.y;
        As[(a_c + 2) * 128 + a_r] = av.z;
        As[(a_c + 3) * 128 + a_r] = av.w;
        *(float4*)&Bs[b_r * 256 + b_c]       = *(const float4*)(Bp + (size_t)k0 * N);
        *(float4*)&Bs[(b_r + 8) * 256 + b_c] = *(const float4*)(Bp + (size_t)(k0 + 8) * N);
        __syncthreads();

#pragma unroll
        for (int kk = 0; kk < 16; kk++) {
            float ar[8];
            *(float4*)&ar[0] = *(const float4*)&As[kk * 128 + ty * 8];
            *(float4*)&ar[4] = *(const float4*)&As[kk * 128 + ty * 8 + 4];
            u64 ar2[8];
#pragma unroll
            for (int i = 0; i < 8; i++) ar2[i] = bcast2(ar[i]);
            const u64* bp64 = (const u64*)&Bs[kk * 256 + tx * 8];
            u64 br2[4];
            br2[0] = bp64[0]; br2[1] = bp64[1]; br2[2] = bp64[2]; br2[3] = bp64[3];
#pragma unroll
            for (int i = 0; i < 8; i++)
#pragma unroll
                for (int j = 0; j < 4; j++)
                    ffma2(acc[i][j], ar2[i], br2[j]);
        }
        __syncthreads();
    }

    // epilogue: + bias, relu, store
    float bb[8];
#pragma unroll
    for (int j = 0; j < 8; j++) bb[j] = bv[n0 + tx * 8 + j];
#pragma unroll
    for (int i = 0; i < 8; i++) {
        const int m = m0 + ty * 8 + i;
        float* crow = C + (size_t)m * N + n0 + tx * 8;
        float o[8];
#pragma unroll
        for (int j = 0; j < 4; j++) {
            float2 v = unpack2(acc[i][j]);
            o[2 * j]     = fmaxf(v.x + bb[2 * j], 0.f);
            o[2 * j + 1] = fmaxf(v.y + bb[2 * j + 1], 0.f);
        }
        *(float4*)crow       = *(float4*)&o[0];
        *(float4*)(crow + 4) = *(float4*)&o[4];
    }
}

// ---------------------------------------------------------------------------
// k_gate3: one warp per token. logits = Y2 @ g3 + gb3; softmax(T=1);
// top-2 on logits; renormalize; sparse p to output; histogram counts.
// ---------------------------------------------------------------------------
__global__ void k_gate3(const float* __restrict__ Y2, const float* __restrict__ g3,
                        const float* __restrict__ gb3, float* __restrict__ p_out)
{
    __shared__ float sg3[NEXP * DIM];   // transposed: [e][k]
    __shared__ float sgb3[NEXP];
    for (int i = threadIdx.x; i < NEXP * DIM; i += blockDim.x) {
        int k = i >> 4, e = i & 15;
        sg3[e * DIM + k] = g3[i];
    }
    if (threadIdx.x < NEXP) sgb3[threadIdx.x] = gb3[threadIdx.x];
    __syncthreads();

    const int gw   = (blockIdx.x * blockDim.x + threadIdx.x) >> 5;  // token
    const int lane = threadIdx.x & 31;

    const float* y = Y2 + (size_t)gw * DIM;
    float yv[8];
#pragma unroll
    for (int i = 0; i < 8; i++) yv[i] = y[lane + 32 * i];

    float l[NEXP];
#pragma unroll
    for (int e = 0; e < NEXP; e++) {
        float s = 0.f;
#pragma unroll
        for (int i = 0; i < 8; i++)
            s = fmaf(yv[i], sg3[e * DIM + lane + 32 * i], s);
        l[e] = s;
    }
#pragma unroll
    for (int off = 16; off > 0; off >>= 1)
#pragma unroll
        for (int e = 0; e < NEXP; e++)
            l[e] += __shfl_xor_sync(0xffffffffu, l[e], off);
#pragma unroll
    for (int e = 0; e < NEXP; e++) l[e] += sgb3[e];

    int i1 = 0; float t1 = l[0];
#pragma unroll
    for (int e = 1; e < NEXP; e++) if (l[e] > t1) { t1 = l[e]; i1 = e; }
    int i2 = -1; float t2 = -INFINITY;
#pragma unroll
    for (int e = 0; e < NEXP; e++) if (e != i1 && l[e] > t2) { t2 = l[e]; i2 = e; }

    const float mx = t1;
    float se = 0.f;
#pragma unroll
    for (int e = 0; e < NEXP; e++) se += expf(l[e] - mx);
    const float inv = 1.f / se;
    const float v1 = expf(t1 - mx) * inv;
    const float v2 = expf(t2 - mx) * inv;
    const float dn = 1.f / (v1 + v2 + 1e-9f);
    const float w0 = v1 * dn, w1 = v2 * dn;

    if (lane < NEXP) {
        float pv = (lane == i1) ? w0 : ((lane == i2) ? w1 : 0.f);
        p_out[(size_t)gw * NEXP + lane] = pv;
    }
    if (lane == 0) {
        g_w[gw * 2 + 0]    = w0;
        g_w[gw * 2 + 1]    = w1;
        g_eidx[gw * 2 + 0] = i1;
        g_eidx[gw * 2 + 1] = i2;
        atomicAdd(&g_counts[i1], 1);
        atomicAdd(&g_counts[i2], 1);
    }
}

// ---------------------------------------------------------------------------
__global__ void k_scan() {
    if (threadIdx.x == 0) {
        int acc = 0;
        for (int i = 0; i < NEXP; i++) {
            g_offsets[i] = acc;
            acc += g_counts[i];
            g_cursor[i] = 0;
        }
        g_offsets[NEXP] = acc;
    }
}

__global__ void k_scatter() {
    int i = blockIdx.x * blockDim.x + threadIdx.x;   // entry = token*2 + slot
    if (i >= BATCH * 2) return;
    int e = g_eidx[i];
    int pos = atomicAdd(&g_cursor[e], 1);
    g_list[g_offsets[e] + pos] = (unsigned)i;
}

// ---------------------------------------------------------------------------
// k_expert: grouped expert GEMM (FFMA2). Each block = 128-row tile of one expert.
//   stage 1: H[128,256] = relu((gather(x)+bias[e]) @ W1[e] + b1[e])  -> smem
//   stage 2: OUT[128,256] = (H @ W2[e] + b2[e]) * w  -> g_yslots rows
// ---------------------------------------------------------------------------
#define HPAD 260
#define EXPERT_SMEM ((128*HPAD + 16*128 + 16*256 + 3*256 + 128) * 4 + 128 * 4)

__global__ __launch_bounds__(512, 1)
void k_expert(const float* __restrict__ x, const float* __restrict__ bias,
              const float* __restrict__ W1, const float* __restrict__ b1,
              const float* __restrict__ W2, const float* __restrict__ b2)
{
    extern __shared__ float sm[];
    float* Hs     = sm;                         // 128*HPAD
    float* As     = Hs + 128 * HPAD;            // 16*128
    float* Bs     = As + 16 * 128;              // 16*256
    float* s_bias = Bs + 16 * 256;              // 256
    float* s_b1   = s_bias + 256;               // 256
    float* s_b2   = s_b1 + 256;                 // 256
    float* s_w    = s_b2 + 256;                 // 128
    int*   s_ent  = (int*)(s_w + 128);          // 128
    __shared__ int s_meta[3];

    const int tid = threadIdx.x;

    if (tid == 0) {
        int bid = blockIdx.x, acc = 0, e = -1, row0 = 0, cnt = 0;
        for (int i = 0; i < NEXP; i++) {
            int c  = g_counts[i];
            int nt = (c + 127) >> 7;
            if (e < 0 && bid < acc + nt) {
                int tt = bid - acc;
                e = i;
                row0 = g_offsets[i] + tt * 128;
                cnt  = c - tt * 128;
                if (cnt > 128) cnt = 128;
            }
            acc += nt;
        }
        s_meta[0] = e; s_meta[1] = row0; s_meta[2] = cnt;
    }
    __syncthreads();

    const int e = s_meta[0];
    if (e < 0) return;
    const int row0 = s_meta[1];
    const int cnt  = s_meta[2];

    if (tid < 128) {
        unsigned ent = g_list[row0 + ((tid < cnt) ? tid : 0)];
        s_ent[tid] = (int)ent;
        s_w[tid]   = g_w[ent];
    }
    for (int i = tid; i < 256; i += 512) {
        s_bias[i] = bias[e * 256 + i];
        s_b1[i]   = b1[e * 256 + i];
        s_b2[i]   = b2[e * 256 + i];
    }
    __syncthreads();

    const int tx = tid & 31, ty = tid >> 5;
    const int a_r = tid >> 2, a_c = (tid & 3) << 2;
    const int b_r = tid >> 6, b_c = (tid & 63) << 2;

    const int tok = s_ent[a_r] >> 1;
    const float* xrow = x + (size_t)tok * DIM;

    u64 acc[8][4];
#pragma unroll
    for (int i = 0; i < 8; i++)
#pragma unroll
        for (int j = 0; j < 4; j++) acc[i][j] = 0ull;

    // ------------------ stage 1: H = relu((x+bias) @ W1 + b1) ---------------
    const float* W1e = W1 + (size_t)e * DIM * HID;
    for (int k0 = 0; k0 < DIM; k0 += 16) {
        float4 av = *(const float4*)(xrow + k0 + a_c);
        float4 bb = *(const float4*)(s_bias + k0 + a_c);
        As[(a_c + 0) * 128 + a_r] = av.x + bb.x;
        As[(a_c + 1) * 128 + a_r] = av.y + bb.y;
        As[(a_c + 2) * 128 + a_r] = av.z + bb.z;
        As[(a_c + 3) * 128 + a_r] = av.w + bb.w;
        *(float4*)&Bs[b_r * 256 + b_c]       = *(const float4*)(W1e + (size_t)(k0 + b_r) * HID + b_c);
        *(float4*)&Bs[(b_r + 8) * 256 + b_c] = *(const float4*)(W1e + (size_t)(k0 + b_r + 8) * HID + b_c);
        __syncthreads();
#pragma unroll
        for (int kk = 0; kk < 16; kk++) {
            float ar[8];
            *(float4*)&ar[0] = *(const float4*)&As[kk * 128 + ty * 8];
            *(float4*)&ar[4] = *(const float4*)&As[kk * 128 + ty * 8 + 4];
            u64 ar2[8];
#pragma unroll
            for (int i = 0; i < 8; i++) ar2[i] = bcast2(ar[i]);
            const u64* bp64 = (const u64*)&Bs[kk * 256 + tx * 8];
            u64 br2[4];
            br2[0] = bp64[0]; br2[1] = bp64[1]; br2[2] = bp64[2]; br2[3] = bp64[3];
#pragma unroll
            for (int i = 0; i < 8; i++)
#pragma unroll
                for (int j = 0; j < 4; j++)
                    ffma2(acc[i][j], ar2[i], br2[j]);
        }
        __syncthreads();
    }
    // write H tile to smem (relu + b1)
#pragma unroll
    for (int i = 0; i < 8; i++) {
        const int m = ty * 8 + i;
        float o[8];
#pragma unroll
        for (int j = 0; j < 4; j++) {
            float2 v = unpack2(acc[i][j]);
            o[2 * j]     = fmaxf(v.x + s_b1[tx * 8 + 2 * j], 0.f);
            o[2 * j + 1] = fmaxf(v.y + s_b1[tx * 8 + 2 * j + 1], 0.f);
        }
        *(float4*)&Hs[m * HPAD + tx * 8]     = *(float4*)&o[0];
        *(float4*)&Hs[m * HPAD + tx * 8 + 4] = *(float4*)&o[4];
    }
    __syncthreads();

    // ------------------ stage 2: OUT = (H @ W2 + b2) * w --------------------
#pragma unroll
    for (int i = 0; i < 8; i++)
#pragma unroll
        for (int j = 0; j < 4; j++) acc[i][j] = 0ull;

    const float* W2e = W2 + (size_t)e * HID * OUTD;
    for (int k0 = 0; k0 < HID; k0 += 16) {
        *(float4*)&Bs[b_r * 256 + b_c]       = *(const float4*)(W2e + (size_t)(k0 + b_r) * OUTD + b_c);
        *(float4*)&Bs[(b_r + 8) * 256 + b_c] = *(const float4*)(W2e + (size_t)(k0 + b_r + 8) * OUTD + b_c);
        __syncthreads();
#pragma unroll
        for (int kk = 0; kk < 16; kk++) {
            u64 ar2[8];
#pragma unroll
            for (int i = 0; i < 8; i++)
                ar2[i] = bcast2(Hs[(ty * 8 + i) * HPAD + k0 + kk]);  // warp-broadcast
            const u64* bp64 = (const u64*)&Bs[kk * 256 + tx * 8];
            u64 br2[4];
            br2[0] = bp64[0]; br2[1] = bp64[1]; br2[2] = bp64[2]; br2[3] = bp64[3];
#pragma unroll
            for (int i = 0; i < 8; i++)
#pragma unroll
                for (int j = 0; j < 4; j++)
                    ffma2(acc[i][j], ar2[i], br2[j]);
        }
        __syncthreads();
    }

#pragma unroll
    for (int i = 0; i < 8; i++) {
        const int m = ty * 8 + i;
        if (m < cnt) {
            const unsigned ent = (unsigned)s_ent[m];
            const float w = s_w[m];
            float* dst = g_yslots + (size_t)ent * OUTD + tx * 8;
            float o[8];
#pragma unroll
            for (int j = 0; j < 4; j++) {
                float2 v = unpack2(acc[i][j]);
                o[2 * j]     = (v.x + s_b2[tx * 8 + 2 * j]) * w;
                o[2 * j + 1] = (v.y + s_b2[tx * 8 + 2 * j + 1]) * w;
            }
            *(float4*)dst       = *(float4*)&o[0];
            *(float4*)(dst + 4) = *(float4*)&o[4];
        }
    }
}

// ---------------------------------------------------------------------------
// k_combine: y[t] = yslots[2t] + yslots[2t+1]
// ---------------------------------------------------------------------------
__global__ void k_combine(float* __restrict__ y)
{
    const int gi = blockIdx.x * blockDim.x + threadIdx.x;  // float4 index
    const int t  = gi >> 6;          // 64 float4 per row
    const int c4 = (gi & 63) << 2;
    const float4 a = *(const float4*)&g_yslots[((size_t)2 * t)     * OUTD + c4];
    const float4 b = *(const float4*)&g_yslots[((size_t)2 * t + 1) * OUTD + c4];
    float4 o;
    o.x = a.x + b.x; o.y = a.y + b.y; o.z = a.z + b.z; o.w = a.w + b.w;
    *(float4*)&y[(size_t)t * OUTD + c4] = o;
}

// ---------------------------------------------------------------------------
extern "C" void kernel_launch(void* const* d_in, const int* in_sizes, int n_in,
                              void* d_out, int out_size)
{
    const float* x    = (const float*)d_in[0];
    const float* bias = (const float*)d_in[1];
    const float* W1   = (const float*)d_in[2];
    const float* b1   = (const float*)d_in[3];
    const float* W2   = (const float*)d_in[4];
    const float* b2   = (const float*)d_in[5];
    const float* g1   = (const float*)d_in[6];
    const float* gb1  = (const float*)d_in[7];
    const float* g2   = (const float*)d_in[8];
    const float* gb2  = (const float*)d_in[9];
    const float* g3   = (const float*)d_in[10];
    const float* gb3  = (const float*)d_in[11];

    float* y_out = (float*)d_out;
    float* p_out = y_out + (size_t)BATCH * OUTD;

    float *Y1p = nullptr, *Y2p = nullptr;
    cudaGetSymbolAddress((void**)&Y1p, g_Y1);
    cudaGetSymbolAddress((void**)&Y2p, g_Y2);

    cudaFuncSetAttribute(k_expert, cudaFuncAttributeMaxDynamicSharedMemorySize,
                         EXPERT_SMEM);

    k_zero<<<1, 32>>>();

    // gate layer 1: [65536,256] @ [256,1024] -> relu
    k_gemm_bias_relu<<<dim3(GHID / 256, BATCH / 128), 512>>>(
        x, g1, gb1, Y1p, BATCH, GHID, DIM);

    // gate layer 2: [65536,1024] @ [1024,256] -> relu
    k_gemm_bias_relu<<<dim3(DIM / 256, BATCH / 128), 512>>>(
        Y1p, g2, gb2, Y2p, BATCH, DIM, GHID);

    // gate layer 3 + softmax + top-2 + p output
    k_gate3<<<BATCH / 8, 256>>>(Y2p, g3, gb3, p_out);

    k_scan<<<1, 1>>>();
    k_scatter<<<(BATCH * 2) / 256, 256>>>();

    // grouped expert GEMM (upper bound on tiles: 2B/128 + E = 1040)
    k_expert<<<1040, 512, EXPERT_SMEM>>>(x, bias, W1, b1, W2, b2);

    // y = slot0 + slot1
    k_combine<<<(BATCH * 64) / 256, 256>>>(y_out);
}

// round 16
// speedup vs baseline: 1.7431x; 1.7431x over previous
#include <cuda_runtime.h>
#include <cuda_bf16.h>
#include <math.h>
#include <stdint.h>

// ---------------------------------------------------------------------------
// MoELayer B=65536, D=256, E=16, H=256, O=256, TOP_K=2
// out = [ y (B*O f32) | p (B*E f32) ]
// R15: R14 + 16B-aligned dynamic smem (extern __shared__ __align__(16)) and
//      aligned static shared arrays -> fixes misaligned-address fault.
// ---------------------------------------------------------------------------

#define BATCH   65536
#define DIM     256
#define NEXP    16
#define HID     256
#define OUTD    256
#define GHID    1024
#define MAXFLAG 8192
#define GAP_TH  2e-3f

typedef unsigned long long u64;
typedef unsigned int       u32;
typedef __nv_bfloat16      bf16;

// ---------------------------- helpers ---------------------------------------
__device__ __forceinline__ u32 smem_u32(const void* p) {
    u32 a;
    asm("{ .reg .u64 t; cvta.to.shared.u64 t, %1; cvt.u32.u64 %0, t; }"
        : "=r"(a) : "l"(p));
    return a;
}
// split two fp32 into packed-bf16x2 hi and lo words
__device__ __forceinline__ void split2(float a, float b, u32& hi, u32& lo) {
    bf16 ha = __float2bfloat16_rn(a), hb = __float2bfloat16_rn(b);
    bf16 la = __float2bfloat16_rn(a - __bfloat162float(ha));
    bf16 lb = __float2bfloat16_rn(b - __bfloat162float(hb));
    __nv_bfloat162 H; H.x = ha; H.y = hb;
    __nv_bfloat162 L; L.x = la; L.y = lb;
    hi = *reinterpret_cast<u32*>(&H);
    lo = *reinterpret_cast<u32*>(&L);
}
__device__ __forceinline__ void ldsm4(u32& r0, u32& r1, u32& r2, u32& r3, u32 a) {
    asm volatile("ldmatrix.sync.aligned.m8n8.x4.shared.b16 {%0,%1,%2,%3}, [%4];"
                 : "=r"(r0), "=r"(r1), "=r"(r2), "=r"(r3) : "r"(a));
}
__device__ __forceinline__ void mma_bf16(float* c, const u32* a, const u32* b) {
    asm volatile(
        "mma.sync.aligned.m16n8k16.row.col.f32.bf16.bf16.f32 "
        "{%0,%1,%2,%3}, {%4,%5,%6,%7}, {%8,%9}, {%0,%1,%2,%3};"
        : "+f"(c[0]), "+f"(c[1]), "+f"(c[2]), "+f"(c[3])
        : "r"(a[0]), "r"(a[1]), "r"(a[2]), "r"(a[3]), "r"(b[0]), "r"(b[1]));
}

#define TSTR 72   // smem tile row stride in bf16 (64 + 8 pad; 144B = 9*16B rows)
#define TILE_BYTES (128 * TSTR * 2)
#define DYN_SMEM (4 * TILE_BYTES)

// 16B-aligned dynamic smem declaration used by all tensor kernels
#define DECL_DYN_SMEM extern __shared__ __align__(16) char sm[]

// ---------------------------- scratch (16B-aligned) -------------------------
__device__ __align__(16) bf16 g_xh[(size_t)BATCH * DIM];
__device__ __align__(16) bf16 g_xl[(size_t)BATCH * DIM];
__device__ __align__(16) bf16 g_Y1h[(size_t)BATCH * GHID];
__device__ __align__(16) bf16 g_Y1l[(size_t)BATCH * GHID];
__device__ __align__(16) float g_Y2[(size_t)BATCH * DIM];
__device__ __align__(16) bf16 g_Hh[(size_t)BATCH * 2 * HID];
__device__ __align__(16) bf16 g_Hl[(size_t)BATCH * 2 * HID];
__device__ __align__(16) bf16 g_g1th[GHID * DIM];
__device__ __align__(16) bf16 g_g1tl[GHID * DIM];
__device__ __align__(16) bf16 g_g2th[DIM * GHID];
__device__ __align__(16) bf16 g_g2tl[DIM * GHID];
__device__ __align__(16) bf16 g_W1th[NEXP * DIM * HID];
__device__ __align__(16) bf16 g_W1tl[NEXP * DIM * HID];
__device__ __align__(16) bf16 g_W2th[NEXP * HID * OUTD];
__device__ __align__(16) bf16 g_W2tl[NEXP * HID * OUTD];
__device__ __align__(16) float    g_w[BATCH * 2];
__device__ __align__(16) int      g_eidx[BATCH * 2];
__device__ __align__(16) int      g_counts[NEXP];
__device__ __align__(16) int      g_offsets[NEXP + 1];
__device__ __align__(16) int      g_cursor[NEXP];
__device__ __align__(16) unsigned g_list[BATCH * 2];
__device__ __align__(16) float    g_yslots[(size_t)BATCH * 2 * OUTD];
__device__ int g_nflag;
__device__ __align__(16) int   g_flag[MAXFLAG];
__device__ __align__(16) float g_Y1f[(size_t)MAXFLAG * GHID];
__device__ __align__(16) float g_Y2f[(size_t)MAXFLAG * DIM];

// ---------------------------------------------------------------------------
__global__ void k_zero() {
    if (threadIdx.x < NEXP) g_counts[threadIdx.x] = 0;
    if (threadIdx.x == 0) g_nflag = 0;
}

// transpose + bf16 split: src [b][K][N] -> dst [b][N][K]
__global__ void k_prep(const float* __restrict__ src, bf16* __restrict__ hi,
                       bf16* __restrict__ lo, int K, int N, int total) {
    int idx = blockIdx.x * blockDim.x + threadIdx.x;
    if (idx >= total) return;
    int kn = K * N;
    int b = idx / kn, r = idx - b * kn;
    int n = r / K, k = r - n * K;
    float v = src[(size_t)b * kn + (size_t)k * N + n];
    bf16 h = __float2bfloat16_rn(v);
    hi[idx] = h;
    lo[idx] = __float2bfloat16_rn(v - __bfloat162float(h));
}

// split x fp32 -> bf16 hi/lo (row-major kept)
__global__ void k_splitx(const float* __restrict__ x) {
    int i = blockIdx.x * blockDim.x + threadIdx.x;   // per 2 elems
    float2 v = *(const float2*)(x + (size_t)i * 2);
    u32 h, l; split2(v.x, v.y, h, l);
    *(u32*)&g_xh[(size_t)i * 2] = h;
    *(u32*)&g_xl[(size_t)i * 2] = l;
}

// ---------------------------------------------------------------------------
// smem tile fill: [128 x 64] bf16 hi+lo from gmem rows (stride in elems)
// ---------------------------------------------------------------------------
__device__ __forceinline__ void fill_tile(bf16* sh, bf16* sl,
                                          const bf16* gh, const bf16* gl,
                                          size_t rstride, int tid) {
#pragma unroll
    for (int it = 0; it < 4; it++) {
        int idx = tid + it * 256;        // 1024 uint4 per array
        int r = idx >> 3, c = idx & 7;
        *(uint4*)(sh + r * TSTR + c * 8) = *(const uint4*)(gh + (size_t)r * rstride + c * 8);
        *(uint4*)(sl + r * TSTR + c * 8) = *(const uint4*)(gl + (size_t)r * rstride + c * 8);
    }
}

// ---------------------------------------------------------------------------
// per-warp compute over one 128x128x64 chunk. warp (wm in 0..1, wn in 0..3),
// warp tile 64x32, acc[4][4][4].
// ---------------------------------------------------------------------------
__device__ __forceinline__ void compute_chunk(u32 sAh, u32 sAl, u32 sBh, u32 sBl,
                                              int lane, int wm, int wn,
                                              float acc[4][4][4]) {
    const int arow = wm * 64 + (lane & 15);
    const int acol0 = (lane >> 4) << 3;
    const int brow = wn * 32 + (lane & 7) + ((lane >> 4) << 3);
    const int bcol0 = ((lane >> 3) & 1) << 3;
#pragma unroll
    for (int ks = 0; ks < 4; ks++) {
        u32 ah[4][4], al[4][4];
#pragma unroll
        for (int mt = 0; mt < 4; mt++) {
            u32 off = (u32)(((arow + mt * 16) * TSTR + ks * 16 + acol0) * 2);
            ldsm4(ah[mt][0], ah[mt][1], ah[mt][2], ah[mt][3], sAh + off);
            ldsm4(al[mt][0], al[mt][1], al[mt][2], al[mt][3], sAl + off);
        }
        u32 bh[4][2], bl[4][2];
#pragma unroll
        for (int nt2 = 0; nt2 < 2; nt2++) {
            u32 off = (u32)(((brow + nt2 * 16) * TSTR + ks * 16 + bcol0) * 2);
            u32 r0, r1, r2, r3;
            ldsm4(r0, r1, r2, r3, sBh + off);
            bh[nt2 * 2][0] = r0; bh[nt2 * 2][1] = r1;
            bh[nt2 * 2 + 1][0] = r2; bh[nt2 * 2 + 1][1] = r3;
            ldsm4(r0, r1, r2, r3, sBl + off);
            bl[nt2 * 2][0] = r0; bl[nt2 * 2][1] = r1;
            bl[nt2 * 2 + 1][0] = r2; bl[nt2 * 2 + 1][1] = r3;
        }
#pragma unroll
        for (int mt = 0; mt < 4; mt++)
#pragma unroll
            for (int nt = 0; nt < 4; nt++) {
                mma_bf16(acc[mt][nt], ah[mt], bh[nt]);   // hi*hi
                mma_bf16(acc[mt][nt], ah[mt], bl[nt]);   // hi*lo
                mma_bf16(acc[mt][nt], al[mt], bh[nt]);   // lo*hi
            }
    }
}

// ---------------------------------------------------------------------------
// k_gate1: Y1 = relu(x @ g1 + gb1) -> split bf16.  grid (8, 512), 256 thr.
// ---------------------------------------------------------------------------
__global__ __launch_bounds__(256)
void k_gate1(const float* __restrict__ gb1) {
    DECL_DYN_SMEM;
    bf16* Ah = (bf16*)sm;
    bf16* Al = (bf16*)(sm + TILE_BYTES);
    bf16* Bh = (bf16*)(sm + 2 * TILE_BYTES);
    bf16* Bl = (bf16*)(sm + 3 * TILE_BYTES);
    __shared__ __align__(16) float s_bias[128];

    const int tid = threadIdx.x, lane = tid & 31, wid = tid >> 5;
    const int wm = wid >> 2, wn = wid & 3;
    const int n0 = blockIdx.x * 128, m0 = blockIdx.y * 128;
    if (tid < 128) s_bias[tid] = gb1[n0 + tid];

    const u32 sAh = smem_u32(Ah), sAl = smem_u32(Al);
    const u32 sBh = smem_u32(Bh), sBl = smem_u32(Bl);
    float acc[4][4][4];
#pragma unroll
    for (int i = 0; i < 4; i++)
#pragma unroll
        for (int j = 0; j < 4; j++)
#pragma unroll
            for (int q = 0; q < 4; q++) acc[i][j][q] = 0.f;

    for (int k0 = 0; k0 < DIM; k0 += 64) {
        __syncthreads();
        fill_tile(Ah, Al, g_xh + (size_t)m0 * DIM + k0, g_xl + (size_t)m0 * DIM + k0, DIM, tid);
        fill_tile(Bh, Bl, g_g1th + (size_t)n0 * DIM + k0, g_g1tl + (size_t)n0 * DIM + k0, DIM, tid);
        __syncthreads();
        compute_chunk(sAh, sAl, sBh, sBl, lane, wm, wn, acc);
    }
#pragma unroll
    for (int mt = 0; mt < 4; mt++) {
        const int r = m0 + wm * 64 + mt * 16 + (lane >> 2);
#pragma unroll
        for (int nt = 0; nt < 4; nt++) {
            const int cl = wn * 32 + nt * 8 + (lane & 3) * 2;
            const int c = n0 + cl;
            float* a = acc[mt][nt];
            u32 h, l;
            split2(fmaxf(a[0] + s_bias[cl], 0.f), fmaxf(a[1] + s_bias[cl + 1], 0.f), h, l);
            *(u32*)&g_Y1h[(size_t)r * GHID + c] = h;
            *(u32*)&g_Y1l[(size_t)r * GHID + c] = l;
            split2(fmaxf(a[2] + s_bias[cl], 0.f), fmaxf(a[3] + s_bias[cl + 1], 0.f), h, l);
            *(u32*)&g_Y1h[(size_t)(r + 8) * GHID + c] = h;
            *(u32*)&g_Y1l[(size_t)(r + 8) * GHID + c] = l;
        }
    }
}

// ---------------------------------------------------------------------------
// k_gate2: Y2 = relu(Y1 @ g2 + gb2) -> fp32.  grid (2, 512), 256 thr.
// ---------------------------------------------------------------------------
__global__ __launch_bounds__(256)
void k_gate2(const float* __restrict__ gb2) {
    DECL_DYN_SMEM;
    bf16* Ah = (bf16*)sm;
    bf16* Al = (bf16*)(sm + TILE_BYTES);
    bf16* Bh = (bf16*)(sm + 2 * TILE_BYTES);
    bf16* Bl = (bf16*)(sm + 3 * TILE_BYTES);
    __shared__ __align__(16) float s_bias[128];

    const int tid = threadIdx.x, lane = tid & 31, wid = tid >> 5;
    const int wm = wid >> 2, wn = wid & 3;
    const int n0 = blockIdx.x * 128, m0 = blockIdx.y * 128;
    if (tid < 128) s_bias[tid] = gb2[n0 + tid];

    const u32 sAh = smem_u32(Ah), sAl = smem_u32(Al);
    const u32 sBh = smem_u32(Bh), sBl = smem_u32(Bl);
    float acc[4][4][4];
#pragma unroll
    for (int i = 0; i < 4; i++)
#pragma unroll
        for (int j = 0; j < 4; j++)
#pragma unroll
            for (int q = 0; q < 4; q++) acc[i][j][q] = 0.f;

    for (int k0 = 0; k0 < GHID; k0 += 64) {
        __syncthreads();
        fill_tile(Ah, Al, g_Y1h + (size_t)m0 * GHID + k0, g_Y1l + (size_t)m0 * GHID + k0, GHID, tid);
        fill_tile(Bh, Bl, g_g2th + (size_t)n0 * GHID + k0, g_g2tl + (size_t)n0 * GHID + k0, GHID, tid);
        __syncthreads();
        compute_chunk(sAh, sAl, sBh, sBl, lane, wm, wn, acc);
    }
#pragma unroll
    for (int mt = 0; mt < 4; mt++) {
        const int r = m0 + wm * 64 + mt * 16 + (lane >> 2);
#pragma unroll
        for (int nt = 0; nt < 4; nt++) {
            const int cl = wn * 32 + nt * 8 + (lane & 3) * 2;
            const int c = n0 + cl;
            float* a = acc[mt][nt];
            float2 v0 = {fmaxf(a[0] + s_bias[cl], 0.f), fmaxf(a[1] + s_bias[cl + 1], 0.f)};
            float2 v1 = {fmaxf(a[2] + s_bias[cl], 0.f), fmaxf(a[3] + s_bias[cl + 1], 0.f)};
            *(float2*)&g_Y2[(size_t)r * DIM + c] = v0;
            *(float2*)&g_Y2[(size_t)(r + 8) * DIM + c] = v1;
        }
    }
}

// ---------------------------------------------------------------------------
// k_gate3: fp32 SIMT logits + softmax + top-2; flags near-tie tokens.
// ---------------------------------------------------------------------------
__global__ void k_gate3(const float* __restrict__ g3, const float* __restrict__ gb3,
                        float* __restrict__ p_out) {
    __shared__ float sg3[NEXP * DIM];
    __shared__ float sgb3[NEXP];
    for (int i = threadIdx.x; i < NEXP * DIM; i += blockDim.x) {
        int k = i >> 4, e = i & 15;
        sg3[e * DIM + k] = g3[i];
    }
    if (threadIdx.x < NEXP) sgb3[threadIdx.x] = gb3[threadIdx.x];
    __syncthreads();

    const int gw = (blockIdx.x * blockDim.x + threadIdx.x) >> 5;
    const int lane = threadIdx.x & 31;

    const float* y = g_Y2 + (size_t)gw * DIM;
    float yv[8];
#pragma unroll
    for (int i = 0; i < 8; i++) yv[i] = y[lane + 32 * i];

    float l[NEXP];
#pragma unroll
    for (int e = 0; e < NEXP; e++) {
        float s = 0.f;
#pragma unroll
        for (int i = 0; i < 8; i++)
            s = fmaf(yv[i], sg3[e * DIM + lane + 32 * i], s);
        l[e] = s;
    }
#pragma unroll
    for (int off = 16; off > 0; off >>= 1)
#pragma unroll
        for (int e = 0; e < NEXP; e++)
            l[e] += __shfl_xor_sync(0xffffffffu, l[e], off);
#pragma unroll
    for (int e = 0; e < NEXP; e++) l[e] += sgb3[e];

    int i1 = 0; float t1 = l[0];
#pragma unroll
    for (int e = 1; e < NEXP; e++) if (l[e] > t1) { t1 = l[e]; i1 = e; }
    int i2 = -1; float t2 = -INFINITY;
#pragma unroll
    for (int e = 0; e < NEXP; e++) if (e != i1 && l[e] > t2) { t2 = l[e]; i2 = e; }
    float t3 = -INFINITY;
#pragma unroll
    for (int e = 0; e < NEXP; e++) if (e != i1 && e != i2 && l[e] > t3) t3 = l[e];

    float se = 0.f;
#pragma unroll
    for (int e = 0; e < NEXP; e++) se += expf(l[e] - t1);
    const float inv = 1.f / se;
    const float v1 = inv;
    const float v2 = expf(t2 - t1) * inv;
    const float dn = 1.f / (v1 + v2 + 1e-9f);
    const float w0 = v1 * dn, w1 = v2 * dn;

    if (lane < NEXP) {
        float pv = (lane == i1) ? w0 : ((lane == i2) ? w1 : 0.f);
        p_out[(size_t)gw * NEXP + lane] = pv;
    }
    if (lane == 0) {
        g_w[gw * 2 + 0]    = w0;
        g_w[gw * 2 + 1]    = w1;
        g_eidx[gw * 2 + 0] = i1;
        g_eidx[gw * 2 + 1] = i2;
        atomicAdd(&g_counts[i1], 1);
        atomicAdd(&g_counts[i2], 1);
        if (t2 - t3 < GAP_TH) {
            int s = atomicAdd(&g_nflag, 1);
            if (s < MAXFLAG) g_flag[s] = gw;
        }
    }
}

// ---------------------------------------------------------------------------
// k_gemm_repair: fp32 SIMT GEMM on flagged tokens. tile 128x256, 512 thr.
// ---------------------------------------------------------------------------
__global__ __launch_bounds__(512, 1)
void k_gemm_repair(const float* __restrict__ A, const float* __restrict__ B,
                   const float* __restrict__ bv, float* __restrict__ C,
                   int N, int K, int gather) {
    int cnt = g_nflag; if (cnt > MAXFLAG) cnt = MAXFLAG;
    const int m0 = blockIdx.y * 128;
    if (m0 >= cnt) return;
    __shared__ __align__(16) float As[16 * 128];
    __shared__ __align__(16) float Bs[16 * 256];

    const int tid = threadIdx.x;
    const int tx = tid & 31, ty = tid >> 5;
    const int n0 = blockIdx.x * 256;
    const int a_r = tid >> 2, a_c = (tid & 3) << 2;
    const int b_r = tid >> 6, b_c = (tid & 63) << 2;

    int row = m0 + a_r; if (row >= cnt) row = cnt - 1;
    const float* Arow = gather ? (A + (size_t)g_flag[row] * K)
                               : (A + (size_t)row * K);
    const float* Bp = B + (size_t)b_r * N + n0 + b_c;

    float acc[8][8];
#pragma unroll
    for (int i = 0; i < 8; i++)
#pragma unroll
        for (int j = 0; j < 8; j++) acc[i][j] = 0.f;

    for (int k0 = 0; k0 < K; k0 += 16) {
        float4 av = *(const float4*)(Arow + k0 + a_c);
        As[(a_c + 0) * 128 + a_r] = av.x;
        As[(a_c + 1) * 128 + a_r] = av.y;
        As[(a_c + 2) * 128 + a_r] = av.z;
        As[(a_c + 3) * 128 + a_r] = av.w;
        *(float4*)&Bs[b_r * 256 + b_c]       = *(const float4*)(Bp + (size_t)k0 * N);
        *(float4*)&Bs[(b_r + 8) * 256 + b_c] = *(const float4*)(Bp + (size_t)(k0 + 8) * N);
        __syncthreads();
#pragma unroll
        for (int kk = 0; kk < 16; kk++) {
            float ar[8], br[8];
            *(float4*)&ar[0] = *(const float4*)&As[kk * 128 + ty * 8];
            *(float4*)&ar[4] = *(const float4*)&As[kk * 128 + ty * 8 + 4];
            *(float4*)&br[0] = *(const float4*)&Bs[kk * 256 + tx * 8];
            *(float4*)&br[4] = *(const float4*)&Bs[kk * 256 + tx * 8 + 4];
#pragma unroll
            for (int i = 0; i < 8; i++)
#pragma unroll
                for (int j = 0; j < 8; j++)
                    acc[i][j] = fmaf(ar[i], br[j], acc[i][j]);
        }
        __syncthreads();
    }
#pragma unroll
    for (int i = 0; i < 8; i++) {
        const int m = m0 + ty * 8 + i;
        float* crow = C + (size_t)m * N + n0 + tx * 8;
        float o[8];
#pragma unroll
        for (int j = 0; j < 8; j++)
            o[j] = fmaxf(acc[i][j] + bv[n0 + tx * 8 + j], 0.f);
        *(float4*)crow       = *(float4*)&o[0];
        *(float4*)(crow + 4) = *(float4*)&o[4];
    }
}

// ---------------------------------------------------------------------------
// k_repair3: exact fp32 gate3 for flagged tokens; patch p/w/eidx/counts.
// ---------------------------------------------------------------------------
__global__ void k_repair3(const float* __restrict__ g3, const float* __restrict__ gb3,
                          float* __restrict__ p_out) {
    __shared__ float sg3[NEXP * DIM];
    __shared__ float sgb3[NEXP];
    for (int i = threadIdx.x; i < NEXP * DIM; i += blockDim.x) {
        int k = i >> 4, e = i & 15;
        sg3[e * DIM + k] = g3[i];
    }
    if (threadIdx.x < NEXP) sgb3[threadIdx.x] = gb3[threadIdx.x];
    __syncthreads();

    const int slot = (blockIdx.x * blockDim.x + threadIdx.x) >> 5;
    const int lane = threadIdx.x & 31;
    int cnt = g_nflag; if (cnt > MAXFLAG) cnt = MAXFLAG;
    if (slot >= cnt) return;
    const int token = g_flag[slot];

    const float* y = g_Y2f + (size_t)slot * DIM;
    float yv[8];
#pragma unroll
    for (int i = 0; i < 8; i++) yv[i] = y[lane + 32 * i];

    float l[NEXP];
#pragma unroll
    for (int e = 0; e < NEXP; e++) {
        float s = 0.f;
#pragma unroll
        for (int i = 0; i < 8; i++)
            s = fmaf(yv[i], sg3[e * DIM + lane + 32 * i], s);
        l[e] = s;
    }
#pragma unroll
    for (int off = 16; off > 0; off >>= 1)
#pragma unroll
        for (int e = 0; e < NEXP; e++)
            l[e] += __shfl_xor_sync(0xffffffffu, l[e], off);
#pragma unroll
    for (int e = 0; e < NEXP; e++) l[e] += sgb3[e];

    int i1 = 0; float t1 = l[0];
#pragma unroll
    for (int e = 1; e < NEXP; e++) if (l[e] > t1) { t1 = l[e]; i1 = e; }
    int i2 = -1; float t2 = -INFINITY;
#pragma unroll
    for (int e = 0; e < NEXP; e++) if (e != i1 && l[e] > t2) { t2 = l[e]; i2 = e; }

    float se = 0.f;
#pragma unroll
    for (int e = 0; e < NEXP; e++) se += expf(l[e] - t1);
    const float inv = 1.f / se;
    const float v1 = inv;
    const float v2 = expf(t2 - t1) * inv;
    const float dn = 1.f / (v1 + v2 + 1e-9f);
    const float w0 = v1 * dn, w1 = v2 * dn;

    if (lane < NEXP) {
        float pv = (lane == i1) ? w0 : ((lane == i2) ? w1 : 0.f);
        p_out[(size_t)token * NEXP + lane] = pv;
    }
    if (lane == 0) {
        int o1 = g_eidx[token * 2], o2 = g_eidx[token * 2 + 1];
        if (o1 != i1 || o2 != i2) {
            atomicAdd(&g_counts[o1], -1);
            atomicAdd(&g_counts[o2], -1);
            atomicAdd(&g_counts[i1], 1);
            atomicAdd(&g_counts[i2], 1);
        }
        g_w[token * 2 + 0]    = w0;
        g_w[token * 2 + 1]    = w1;
        g_eidx[token * 2 + 0] = i1;
        g_eidx[token * 2 + 1] = i2;
    }
}

// ---------------------------------------------------------------------------
__global__ void k_scan() {
    if (threadIdx.x == 0) {
        int acc = 0;
        for (int i = 0; i < NEXP; i++) {
            g_offsets[i] = acc;
            acc += g_counts[i];
            g_cursor[i] = 0;
        }
        g_offsets[NEXP] = acc;
    }
}
__global__ void k_scatter() {
    int i = blockIdx.x * blockDim.x + threadIdx.x;
    if (i >= BATCH * 2) return;
    int e = g_eidx[i];
    int pos = atomicAdd(&g_cursor[e], 1);
    g_list[g_offsets[e] + pos] = (unsigned)i;
}

// ---------------------------------------------------------------------------
// expert meta: block -> (expert, row0, cnt); grid.x = 2 * 1040 (n-half in bit0)
// ---------------------------------------------------------------------------
__device__ __forceinline__ void expert_meta(int bid, int* s_meta, int tid) {
    if (tid == 0) {
        int acc = 0, e = -1, row0 = 0, cnt = 0;
        for (int i = 0; i < NEXP; i++) {
            int c  = g_counts[i];
            int nt = (c + 127) >> 7;
            if (e < 0 && bid < acc + nt) {
                int tt = bid - acc;
                e = i;
                row0 = g_offsets[i] + tt * 128;
                cnt  = c - tt * 128;
                if (cnt > 128) cnt = 128;
            }
            acc += nt;
        }
        s_meta[0] = e; s_meta[1] = row0; s_meta[2] = cnt;
    }
}

// ---------------------------------------------------------------------------
// k_exp1: H = relu((gather(x)+bias[e]) @ W1[e]^T + b1[e]) -> split bf16 rows
// ---------------------------------------------------------------------------
__global__ __launch_bounds__(256)
void k_exp1(const float* __restrict__ x, const float* __restrict__ bias,
            const float* __restrict__ b1) {
    DECL_DYN_SMEM;
    bf16* Ah = (bf16*)sm;
    bf16* Al = (bf16*)(sm + TILE_BYTES);
    bf16* Bh = (bf16*)(sm + 2 * TILE_BYTES);
    bf16* Bl = (bf16*)(sm + 3 * TILE_BYTES);
    __shared__ __align__(16) int   s_meta[4];
    __shared__ __align__(16) int   s_tok[128];
    __shared__ __align__(16) float s_biasx[256];
    __shared__ __align__(16) float s_b1[128];

    const int tid = threadIdx.x, lane = tid & 31, wid = tid >> 5;
    const int wm = wid >> 2, wn = wid & 3;
    const int n0 = (blockIdx.x & 1) * 128;

    expert_meta(blockIdx.x >> 1, s_meta, tid);
    __syncthreads();
    const int e = s_meta[0];
    if (e < 0) return;
    const int row0 = s_meta[1], cnt = s_meta[2];

    if (tid < 128) {
        unsigned ent = g_list[row0 + ((tid < cnt) ? tid : 0)];
        s_tok[tid] = (int)(ent >> 1);
        s_b1[tid]  = b1[e * 256 + n0 + tid];
    }
    s_biasx[tid] = bias[e * 256 + tid];
    __syncthreads();

    const u32 sAh = smem_u32(Ah), sAl = smem_u32(Al);
    const u32 sBh = smem_u32(Bh), sBl = smem_u32(Bl);
    float acc[4][4][4];
#pragma unroll
    for (int i = 0; i < 4; i++)
#pragma unroll
        for (int j = 0; j < 4; j++)
#pragma unroll
            for (int q = 0; q < 4; q++) acc[i][j][q] = 0.f;

    for (int k0 = 0; k0 < DIM; k0 += 64) {
        __syncthreads();
        // A: gather x + expert bias, split on the fly
#pragma unroll
        for (int it = 0; it < 8; it++) {
            int idx = tid + it * 256;       // 2048 float4 groups
            int r = idx >> 4, c4 = idx & 15;
            float4 v = *(const float4*)(x + (size_t)s_tok[r] * DIM + k0 + c4 * 4);
            float4 bb = *(const float4*)(s_biasx + k0 + c4 * 4);
            u32 h0, l0, h1, l1;
            split2(v.x + bb.x, v.y + bb.y, h0, l0);
            split2(v.z + bb.z, v.w + bb.w, h1, l1);
            uint2 H = {h0, h1}, L = {l0, l1};
            *(uint2*)(Ah + r * TSTR + c4 * 4) = H;
            *(uint2*)(Al + r * TSTR + c4 * 4) = L;
        }
        fill_tile(Bh, Bl, g_W1th + ((size_t)e * 256 + n0) * DIM + k0,
                  g_W1tl + ((size_t)e * 256 + n0) * DIM + k0, DIM, tid);
        __syncthreads();
        compute_chunk(sAh, sAl, sBh, sBl, lane, wm, wn, acc);
    }
#pragma unroll
    for (int mt = 0; mt < 4; mt++) {
        const int lr = wm * 64 + mt * 16 + (lane >> 2);
#pragma unroll
        for (int nt = 0; nt < 4; nt++) {
            const int cl = wn * 32 + nt * 8 + (lane & 3) * 2;
            const int c = n0 + cl;
            float* a = acc[mt][nt];
            if (lr < cnt) {
                u32 h, l;
                split2(fmaxf(a[0] + s_b1[cl], 0.f), fmaxf(a[1] + s_b1[cl + 1], 0.f), h, l);
                *(u32*)&g_Hh[(size_t)(row0 + lr) * HID + c] = h;
                *(u32*)&g_Hl[(size_t)(row0 + lr) * HID + c] = l;
            }
            if (lr + 8 < cnt) {
                u32 h, l;
                split2(fmaxf(a[2] + s_b1[cl], 0.f), fmaxf(a[3] + s_b1[cl + 1], 0.f), h, l);
                *(u32*)&g_Hh[(size_t)(row0 + lr + 8) * HID + c] = h;
                *(u32*)&g_Hl[(size_t)(row0 + lr + 8) * HID + c] = l;
            }
        }
    }
}

// ---------------------------------------------------------------------------
// k_exp2: OUT = (H @ W2[e]^T + b2[e]) * w -> g_yslots rows
// ---------------------------------------------------------------------------
__global__ __launch_bounds__(256)
void k_exp2(const float* __restrict__ b2) {
    DECL_DYN_SMEM;
    bf16* Ah = (bf16*)sm;
    bf16* Al = (bf16*)(sm + TILE_BYTES);
    bf16* Bh = (bf16*)(sm + 2 * TILE_BYTES);
    bf16* Bl = (bf16*)(sm + 3 * TILE_BYTES);
    __shared__ __align__(16) int   s_meta[4];
    __shared__ __align__(16) int   s_ent[128];
    __shared__ __align__(16) float s_w[128];
    __shared__ __align__(16) float s_b2[128];

    const int tid = threadIdx.x, lane = tid & 31, wid = tid >> 5;
    const int wm = wid >> 2, wn = wid & 3;
    const int n0 = (blockIdx.x & 1) * 128;

    expert_meta(blockIdx.x >> 1, s_meta, tid);
    __syncthreads();
    const int e = s_meta[0];
    if (e < 0) return;
    const int row0 = s_meta[1], cnt = s_meta[2];

    if (tid < 128) {
        unsigned ent = g_list[row0 + ((tid < cnt) ? tid : 0)];
        s_ent[tid] = (int)ent;
        s_w[tid]   = g_w[ent];
        s_b2[tid]  = b2[e * 256 + n0 + tid];
    }
    __syncthreads();

    const u32 sAh = smem_u32(Ah), sAl = smem_u32(Al);
    const u32 sBh = smem_u32(Bh), sBl = smem_u32(Bl);
    float acc[4][4][4];
#pragma unroll
    for (int i = 0; i < 4; i++)
#pragma unroll
        for (int j = 0; j < 4; j++)
#pragma unroll
            for (int q = 0; q < 4; q++) acc[i][j][q] = 0.f;

    for (int k0 = 0; k0 < HID; k0 += 64) {
        __syncthreads();
        fill_tile(Ah, Al, g_Hh + (size_t)row0 * HID + k0, g_Hl + (size_t)row0 * HID + k0, HID, tid);
        fill_tile(Bh, Bl, g_W2th + ((size_t)e * 256 + n0) * HID + k0,
                  g_W2tl + ((size_t)e * 256 + n0) * HID + k0, HID, tid);
        __syncthreads();
        compute_chunk(sAh, sAl, sBh, sBl, lane, wm, wn, acc);
    }
#pragma unroll
    for (int mt = 0; mt < 4; mt++) {
        const int lr = wm * 64 + mt * 16 + (lane >> 2);
#pragma unroll
        for (int nt = 0; nt < 4; nt++) {
            const int cl = wn * 32 + nt * 8 + (lane & 3) * 2;
            const int c = n0 + cl;
            float* a = acc[mt][nt];
            if (lr < cnt) {
                const float w = s_w[lr];
                float2 v = {(a[0] + s_b2[cl]) * w, (a[1] + s_b2[cl + 1]) * w};
                *(float2*)&g_yslots[(size_t)s_ent[lr] * OUTD + c] = v;
            }
            if (lr + 8 < cnt) {
                const float w = s_w[lr + 8];
                float2 v = {(a[2] + s_b2[cl]) * w, (a[3] + s_b2[cl + 1]) * w};
                *(float2*)&g_yslots[(size_t)s_ent[lr + 8] * OUTD + c] = v;
            }
        }
    }
}

// ---------------------------------------------------------------------------
__global__ void k_combine(float* __restrict__ y) {
    const int gi = blockIdx.x * blockDim.x + threadIdx.x;
    const int t  = gi >> 6;
    const int c4 = (gi & 63) << 2;
    const float4 a = *(const float4*)&g_yslots[((size_t)2 * t)     * OUTD + c4];
    const float4 b = *(const float4*)&g_yslots[((size_t)2 * t + 1) * OUTD + c4];
    float4 o;
    o.x = a.x + b.x; o.y = a.y + b.y; o.z = a.z + b.z; o.w = a.w + b.w;
    *(float4*)&y[(size_t)t * OUTD + c4] = o;
}

// ---------------------------------------------------------------------------
extern "C" void kernel_launch(void* const* d_in, const int* in_sizes, int n_in,
                              void* d_out, int out_size)
{
    const float* x    = (const float*)d_in[0];
    const float* bias = (const float*)d_in[1];
    const float* W1   = (const float*)d_in[2];
    const float* b1   = (const float*)d_in[3];
    const float* W2   = (const float*)d_in[4];
    const float* b2   = (const float*)d_in[5];
    const float* g1   = (const float*)d_in[6];
    const float* gb1  = (const float*)d_in[7];
    const float* g2   = (const float*)d_in[8];
    const float* gb2  = (const float*)d_in[9];
    const float* g3   = (const float*)d_in[10];
    const float* gb3  = (const float*)d_in[11];

    float* y_out = (float*)d_out;
    float* p_out = y_out + (size_t)BATCH * OUTD;

    bf16 *g1th, *g1tl, *g2th, *g2tl, *W1th, *W1tl, *W2th, *W2tl;
    float *Y1f, *Y2f;
    cudaGetSymbolAddress((void**)&g1th, g_g1th); cudaGetSymbolAddress((void**)&g1tl, g_g1tl);
    cudaGetSymbolAddress((void**)&g2th, g_g2th); cudaGetSymbolAddress((void**)&g2tl, g_g2tl);
    cudaGetSymbolAddress((void**)&W1th, g_W1th); cudaGetSymbolAddress((void**)&W1tl, g_W1tl);
    cudaGetSymbolAddress((void**)&W2th, g_W2th); cudaGetSymbolAddress((void**)&W2tl, g_W2tl);
    cudaGetSymbolAddress((void**)&Y1f, g_Y1f);   cudaGetSymbolAddress((void**)&Y2f, g_Y2f);

    cudaFuncSetAttribute(k_gate1, cudaFuncAttributeMaxDynamicSharedMemorySize, DYN_SMEM);
    cudaFuncSetAttribute(k_gate2, cudaFuncAttributeMaxDynamicSharedMemorySize, DYN_SMEM);
    cudaFuncSetAttribute(k_exp1,  cudaFuncAttributeMaxDynamicSharedMemorySize, DYN_SMEM);
    cudaFuncSetAttribute(k_exp2,  cudaFuncAttributeMaxDynamicSharedMemorySize, DYN_SMEM);

    k_zero<<<1, 32>>>();

    // weight transpose + split, x split
    k_prep<<<(DIM * GHID) / 256, 256>>>(g1, g1th, g1tl, DIM, GHID, DIM * GHID);
    k_prep<<<(GHID * DIM) / 256, 256>>>(g2, g2th, g2tl, GHID, DIM, GHID * DIM);
    k_prep<<<(NEXP * DIM * HID) / 256, 256>>>(W1, W1th, W1tl, DIM, HID, NEXP * DIM * HID);
    k_prep<<<(NEXP * HID * OUTD) / 256, 256>>>(W2, W2th, W2tl, HID, OUTD, NEXP * HID * OUTD);
    k_splitx<<<(BATCH * DIM / 2) / 256, 256>>>(x);

    // gate (tensor) + fp32 gate3 with flagging
    k_gate1<<<dim3(8, 512), 256, DYN_SMEM>>>(gb1);
    k_gate2<<<dim3(2, 512), 256, DYN_SMEM>>>(gb2);
    k_gate3<<<BATCH / 8, 256>>>(g3, gb3, p_out);

    // exact repair of near-tie tokens
    k_gemm_repair<<<dim3(4, MAXFLAG / 128), 512>>>(x,   g1, gb1, Y1f, GHID, DIM, 1);
    k_gemm_repair<<<dim3(1, MAXFLAG / 128), 512>>>(Y1f, g2, gb2, Y2f, DIM, GHID, 0);
    k_repair3<<<MAXFLAG / 8, 256>>>(g3, gb3, p_out);

    k_scan<<<1, 1>>>();
    k_scatter<<<(BATCH * 2) / 256, 256>>>();

    // experts (tensor) + combine
    k_exp1<<<2 * 1040, 256, DYN_SMEM>>>(x, bias, b1);
    k_exp2<<<2 * 1040, 256, DYN_SMEM>>>(b2);
    k_combine<<<(BATCH * 64) / 256, 256>>>(y_out);
}